// round 15
// baseline (speedup 1.0000x reference)
#include <cuda_runtime.h>
#include <cuda_bf16.h>
#include <cstdint>

#define EPS       0.1f
#define CHUNKS    16         // blocks per row in the dense kernel
#define TA        128        // threads, dense kernel
#define TB        128        // threads, finalize kernel
#define NEG_LOG2E -1.4426950408889634f
#define LN2       0.6931471805599453f

__device__ float g_partial[65536];   // 4096 rows * 16 chunks

__device__ __forceinline__ float ex2f(float x) {
    float r; asm("ex2.approx.f32 %0, %1;" : "=f"(r) : "f"(x)); return r;
}
__device__ __forceinline__ float lg2f(float x) {
    float r; asm("lg2.approx.f32 %0, %1;" : "=f"(r) : "f"(x)); return r;
}
// Intrinsic-precision log-sigmoid for sparse/tail terms.
__device__ __forceinline__ float logsig_exact(float x) {
    float e = __expf(-fabsf(x));
    return fminf(x, 0.0f) - __logf(1.0f + e);
}

// ---------------- Kernel A: dense partial sums, 16 blocks per row ----------------
// partial[blk] = sum over chunk of lg2(1 + ex2(-x*log2e))   [= -logsig(x)/ln2]
// 4 instructions per element: FMUL, EX2(MUFU), FADD, LG2(MUFU).
__global__ __launch_bounds__(TA) void dense_partial_kernel(
    const float* __restrict__ mat, int num_type, int nvec4, int f4pc)
{
    const int blk   = blockIdx.x;
    const int row   = blk >> 4;          // CHUNKS == 16
    const int chunk = blk & (CHUNKS - 1);
    const int tid   = threadIdx.x;

    const float4* rowv = (const float4*)(mat + (size_t)row * (size_t)num_type);
    const int beg = chunk * f4pc;
    const int end = min(beg + f4pc, nvec4);

    float L0 = 0.0f, L1 = 0.0f;   // two chains to hide FADD latency

    #pragma unroll 4
    for (int i = beg + tid; i < end; i += TA) {
        float4 v = __ldcs(rowv + i);     // read-once: evict-first

        float e0 = ex2f(v.x * NEG_LOG2E);
        float e1 = ex2f(v.y * NEG_LOG2E);
        float e2 = ex2f(v.z * NEG_LOG2E);
        float e3 = ex2f(v.w * NEG_LOG2E);

        L0 += lg2f(1.0f + e0);
        L1 += lg2f(1.0f + e1);
        L0 += lg2f(1.0f + e2);
        L1 += lg2f(1.0f + e3);
    }

    float p = L0 + L1;

    __shared__ float warpsum[TA / 32];
    #pragma unroll
    for (int o = 16; o > 0; o >>= 1)
        p += __shfl_down_sync(0xffffffffu, p, o);
    if ((tid & 31) == 0) warpsum[tid >> 5] = p;
    __syncthreads();
    if (tid < TA / 32) {
        float v = warpsum[tid];
        #pragma unroll
        for (int o = TA / 64; o > 0; o >>= 1)
            v += __shfl_down_sync(0xfu, v, o);
        if (tid == 0) g_partial[blk] = v;
    }
}

// ---------------- Kernel B: per-row finalize (branchless dedup + combine) ----------------
__global__ __launch_bounds__(TB) void finalize_kernel(
    const float* __restrict__ mat,
    const int*   __restrict__ label,
    const int*   __restrict__ test_label,
    float*       __restrict__ out,
    int num_type, int L, int nvec4)
{
    const int b    = blockIdx.x;
    const int tid  = threadIdx.x;
    const int twoL = 2 * L;

    __shared__ int   lab[128];
    __shared__ float warpsum[TB / 32];

    if (tid < L)         lab[tid] = label[b * L + tid];
    else if (tid < twoL) lab[tid] = test_label[b * L + (tid - L)];
    __syncthreads();

    const float  c0  = EPS / (float)num_type;
    const float* row = mat + (size_t)b * (size_t)num_type;

    float acc = 0.0f;

    // dense partials: logsig-sum = -ln2 * partial  (fixed order -> deterministic)
    if (tid < CHUNKS) acc += (-LN2 * c0) * g_partial[b * CHUNKS + tid];

    // scalar tail beyond float4 region (empty when num_type % 4 == 0)
    for (int i = (nvec4 << 2) + tid; i < num_type; i += TB)
        acc += c0 * logsig_exact(row[i]);

    // ---- sparse corrections: branchless dedup (no data-dependent breaks) ----
    if (tid < twoL) {
        const int raw = lab[tid];
        int dup = (raw == 0);            // padding counts as non-canonical
        if (tid >= L) {
            #pragma unroll 5
            for (int k = L; k < twoL; k++)
                dup |= (k < tid) & (lab[k] == raw);
        } else {
            #pragma unroll 5
            for (int k = 0; k < L; k++)
                dup |= (k < tid) & (lab[k] == raw);
            #pragma unroll 5
            for (int k = L; k < twoL; k++)
                dup |= (lab[k] == raw);
        }
        const float w = dup ? 0.0f
                            : ((tid >= L) ? (2.0f * (1.0f - EPS) - 2.0f * c0)
                                          : ((1.0f - EPS) - c0));
        const int j = (raw > 0) ? (raw - 1) : 0;   // clamped: load always safe
        acc += w * logsig_exact(__ldg(row + j));
    }

    // block reduction (128 threads)
    #pragma unroll
    for (int o = 16; o > 0; o >>= 1)
        acc += __shfl_down_sync(0xffffffffu, acc, o);
    if ((tid & 31) == 0) warpsum[tid >> 5] = acc;
    __syncthreads();
    if (tid < TB / 32) {
        float v = warpsum[tid];
        #pragma unroll
        for (int o = TB / 64; o > 0; o >>= 1)
            v += __shfl_down_sync(0xfu, v, o);
        if (tid == 0) out[b] = -v;
    }
}

extern "C" void kernel_launch(void* const* d_in, const int* in_sizes, int n_in,
                              void* d_out, int out_size)
{
    const float* output     = (const float*)d_in[0];
    const int*   label      = (const int*)d_in[1];
    const int*   test_label = (const int*)d_in[2];
    float*       out        = (float*)d_out;

    const int B        = out_size;               // 4096
    const int num_type = in_sizes[0] / B;        // 32000
    const int L        = in_sizes[1] / B;        // 50
    const int nvec4    = num_type >> 2;          // 8000
    const int f4pc     = (nvec4 + CHUNKS - 1) / CHUNKS;  // 500

    dense_partial_kernel<<<B * CHUNKS, TA>>>(output, num_type, nvec4, f4pc);
    finalize_kernel<<<B, TB>>>(output, label, test_label, out, num_type, L, nvec4);
}

// round 16
// speedup vs baseline: 1.0017x; 1.0017x over previous
#include <cuda_runtime.h>
#include <cuda_bf16.h>
#include <cstdint>

#define EPS       0.1f
#define CHUNKS    16         // blocks per row in the dense kernel
#define TA        128        // threads, dense kernel
#define TB        128        // threads, finalize kernel
#define NEG_LOG2E -1.4426950408889634f
#define LN2       0.6931471805599453f

__device__ float g_partial[65536];   // 4096 rows * 16 chunks

__device__ __forceinline__ float ex2f(float x) {
    float r; asm("ex2.approx.f32 %0, %1;" : "=f"(r) : "f"(x)); return r;
}
__device__ __forceinline__ float lg2f(float x) {
    float r; asm("lg2.approx.f32 %0, %1;" : "=f"(r) : "f"(x)); return r;
}
// Intrinsic-precision log-sigmoid for sparse/tail terms.
__device__ __forceinline__ float logsig_exact(float x) {
    float e = __expf(-fabsf(x));
    return fminf(x, 0.0f) - __logf(1.0f + e);
}

// ---------------- Kernel A: dense partial sums, 16 blocks per row ----------------
// partial[blk] = sum over chunk of lg2(1 + ex2(-x*log2e))   [= -logsig(x)/ln2]
// 4 instructions per element: FMUL, EX2(MUFU), FADD, LG2(MUFU).
__global__ __launch_bounds__(TA) void dense_partial_kernel(
    const float* __restrict__ mat, int num_type, int nvec4, int f4pc)
{
    const int blk   = blockIdx.x;
    const int row   = blk >> 4;          // CHUNKS == 16
    const int chunk = blk & (CHUNKS - 1);
    const int tid   = threadIdx.x;

    const float4* rowv = (const float4*)(mat + (size_t)row * (size_t)num_type);
    const int beg = chunk * f4pc;
    const int end = min(beg + f4pc, nvec4);

    float L0 = 0.0f, L1 = 0.0f;   // two chains to hide FADD latency

    #pragma unroll 4
    for (int i = beg + tid; i < end; i += TA) {
        float4 v = __ldcs(rowv + i);     // read-once: evict-first

        float e0 = ex2f(v.x * NEG_LOG2E);
        float e1 = ex2f(v.y * NEG_LOG2E);
        float e2 = ex2f(v.z * NEG_LOG2E);
        float e3 = ex2f(v.w * NEG_LOG2E);

        L0 += lg2f(1.0f + e0);
        L1 += lg2f(1.0f + e1);
        L0 += lg2f(1.0f + e2);
        L1 += lg2f(1.0f + e3);
    }

    float p = L0 + L1;

    __shared__ float warpsum[TA / 32];
    #pragma unroll
    for (int o = 16; o > 0; o >>= 1)
        p += __shfl_down_sync(0xffffffffu, p, o);
    if ((tid & 31) == 0) warpsum[tid >> 5] = p;
    __syncthreads();
    if (tid < TA / 32) {
        float v = warpsum[tid];
        #pragma unroll
        for (int o = TA / 64; o > 0; o >>= 1)
            v += __shfl_down_sync(0xfu, v, o);
        if (tid == 0) g_partial[blk] = v;
    }
}

// ---------------- Kernel B: per-row finalize (branchless dedup + combine) ----------------
__global__ __launch_bounds__(TB) void finalize_kernel(
    const float* __restrict__ mat,
    const int*   __restrict__ label,
    const int*   __restrict__ test_label,
    float*       __restrict__ out,
    int num_type, int L, int nvec4)
{
    const int b    = blockIdx.x;
    const int tid  = threadIdx.x;
    const int twoL = 2 * L;

    __shared__ int   lab[128];
    __shared__ float warpsum[TB / 32];

    if (tid < L)         lab[tid] = label[b * L + tid];
    else if (tid < twoL) lab[tid] = test_label[b * L + (tid - L)];
    __syncthreads();

    const float  c0  = EPS / (float)num_type;
    const float* row = mat + (size_t)b * (size_t)num_type;

    float acc = 0.0f;

    // dense partials: logsig-sum = -ln2 * partial  (fixed order -> deterministic)
    if (tid < CHUNKS) acc += (-LN2 * c0) * g_partial[b * CHUNKS + tid];

    // scalar tail beyond float4 region (empty when num_type % 4 == 0)
    for (int i = (nvec4 << 2) + tid; i < num_type; i += TB)
        acc += c0 * logsig_exact(row[i]);

    // ---- sparse corrections: branchless dedup (no data-dependent breaks) ----
    if (tid < twoL) {
        const int raw = lab[tid];
        int dup = (raw == 0);            // padding counts as non-canonical
        if (tid >= L) {
            #pragma unroll 5
            for (int k = L; k < twoL; k++)
                dup |= (k < tid) & (lab[k] == raw);
        } else {
            #pragma unroll 5
            for (int k = 0; k < L; k++)
                dup |= (k < tid) & (lab[k] == raw);
            #pragma unroll 5
            for (int k = L; k < twoL; k++)
                dup |= (lab[k] == raw);
        }
        const float w = dup ? 0.0f
                            : ((tid >= L) ? (2.0f * (1.0f - EPS) - 2.0f * c0)
                                          : ((1.0f - EPS) - c0));
        const int j = (raw > 0) ? (raw - 1) : 0;   // clamped: load always safe
        acc += w * logsig_exact(__ldg(row + j));
    }

    // block reduction (128 threads)
    #pragma unroll
    for (int o = 16; o > 0; o >>= 1)
        acc += __shfl_down_sync(0xffffffffu, acc, o);
    if ((tid & 31) == 0) warpsum[tid >> 5] = acc;
    __syncthreads();
    if (tid < TB / 32) {
        float v = warpsum[tid];
        #pragma unroll
        for (int o = TB / 64; o > 0; o >>= 1)
            v += __shfl_down_sync(0xfu, v, o);
        if (tid == 0) out[b] = -v;
    }
}

extern "C" void kernel_launch(void* const* d_in, const int* in_sizes, int n_in,
                              void* d_out, int out_size)
{
    const float* output     = (const float*)d_in[0];
    const int*   label      = (const int*)d_in[1];
    const int*   test_label = (const int*)d_in[2];
    float*       out        = (float*)d_out;

    const int B        = out_size;               // 4096
    const int num_type = in_sizes[0] / B;        // 32000
    const int L        = in_sizes[1] / B;        // 50
    const int nvec4    = num_type >> 2;          // 8000
    const int f4pc     = (nvec4 + CHUNKS - 1) / CHUNKS;  // 500

    dense_partial_kernel<<<B * CHUNKS, TA>>>(output, num_type, nvec4, f4pc);
    finalize_kernel<<<B, TB>>>(output, label, test_label, out, num_type, L, nvec4);
}

// round 17
// speedup vs baseline: 1.0389x; 1.0371x over previous
#include <cuda_runtime.h>
#include <cuda_bf16.h>
#include <cstdint>

#define EPS       0.1f
#define CHUNKS    16         // blocks per row in the dense kernel
#define TA        128        // threads, dense kernel
#define NEG_LOG2E -1.4426950408889634f
#define LN2       0.6931471805599453f

__device__ float g_partial[65536];   // 4096 rows * 16 chunks
__device__ float g_sparse[4096];     // per-row sparse correction sums

__device__ __forceinline__ float ex2f(float x) {
    float r; asm("ex2.approx.f32 %0, %1;" : "=f"(r) : "f"(x)); return r;
}
__device__ __forceinline__ float lg2f(float x) {
    float r; asm("lg2.approx.f32 %0, %1;" : "=f"(r) : "f"(x)); return r;
}
// Intrinsic-precision log-sigmoid for sparse/tail terms.
__device__ __forceinline__ float logsig_exact(float x) {
    float e = __expf(-fabsf(x));
    return fminf(x, 0.0f) - __logf(1.0f + e);
}

// ---------------- Kernel A: dense partials + (chunk 0 only) sparse work ----------------
// partial[blk] = sum over chunk of lg2(1 + ex2(-x*log2e))   [= -logsig(x)/ln2]
__global__ __launch_bounds__(TA) void dense_partial_kernel(
    const float* __restrict__ mat,
    const int*   __restrict__ label,
    const int*   __restrict__ test_label,
    int num_type, int L, int nvec4, int f4pc)
{
    const int blk   = blockIdx.x;
    const int row   = blk >> 4;          // CHUNKS == 16
    const int chunk = blk & (CHUNKS - 1);
    const int tid   = threadIdx.x;

    __shared__ float warpsum[TA / 32];
    __shared__ int   lab[128];

    const float* rowp = mat + (size_t)row * (size_t)num_type;
    const float4* rowv = (const float4*)rowp;
    const int beg = chunk * f4pc;
    const int end = min(beg + f4pc, nvec4);

    // ---- dense streaming loop (4 inst/elem: FMUL, EX2, FADD, LG2) ----
    float L0 = 0.0f, L1 = 0.0f;
    #pragma unroll 4
    for (int i = beg + tid; i < end; i += TA) {
        float4 v = __ldcs(rowv + i);     // read-once: evict-first
        float e0 = ex2f(v.x * NEG_LOG2E);
        float e1 = ex2f(v.y * NEG_LOG2E);
        float e2 = ex2f(v.z * NEG_LOG2E);
        float e3 = ex2f(v.w * NEG_LOG2E);
        L0 += lg2f(1.0f + e0);
        L1 += lg2f(1.0f + e1);
        L0 += lg2f(1.0f + e2);
        L1 += lg2f(1.0f + e3);
    }

    float p = L0 + L1;
    #pragma unroll
    for (int o = 16; o > 0; o >>= 1)
        p += __shfl_down_sync(0xffffffffu, p, o);
    if ((tid & 31) == 0) warpsum[tid >> 5] = p;
    __syncthreads();
    if (tid == 0)
        g_partial[blk] = warpsum[0] + warpsum[1] + warpsum[2] + warpsum[3];

    if (chunk != 0) return;

    // ======== chunk-0 blocks also do the row's sparse work (overlapped) ========
    const int twoL = 2 * L;
    if (tid < L)         lab[tid] = label[row * L + tid];
    else if (tid < twoL) lab[tid] = test_label[row * L + (tid - L)];
    __syncthreads();   // also protects warpsum reuse below

    const float c0 = EPS / (float)num_type;
    float acc = 0.0f;

    // scalar tail beyond float4 region (empty when num_type % 4 == 0)
    for (int i = (nvec4 << 2) + tid; i < num_type; i += TA)
        acc += c0 * logsig_exact(rowp[i]);

    // branchless dedup (padding dropped; dedup within lists; test overwrites label)
    if (tid < twoL) {
        const int raw = lab[tid];
        int dup = (raw == 0);
        if (tid >= L) {
            #pragma unroll 5
            for (int k = L; k < twoL; k++)
                dup |= (k < tid) & (lab[k] == raw);
        } else {
            #pragma unroll 5
            for (int k = 0; k < L; k++)
                dup |= (k < tid) & (lab[k] == raw);
            #pragma unroll 5
            for (int k = L; k < twoL; k++)
                dup |= (lab[k] == raw);
        }
        const float w = dup ? 0.0f
                            : ((tid >= L) ? (2.0f * (1.0f - EPS) - 2.0f * c0)
                                          : ((1.0f - EPS) - c0));
        const int j = (raw > 0) ? (raw - 1) : 0;   // clamped: load always safe
        acc += w * logsig_exact(__ldg(rowp + j));
    }

    // second block reduction -> g_sparse[row]
    #pragma unroll
    for (int o = 16; o > 0; o >>= 1)
        acc += __shfl_down_sync(0xffffffffu, acc, o);
    if ((tid & 31) == 0) warpsum[tid >> 5] = acc;
    __syncthreads();
    if (tid == 0)
        g_sparse[row] = warpsum[0] + warpsum[1] + warpsum[2] + warpsum[3];
}

// ---------------- Kernel B: trivial combine (one warp per row) ----------------
__global__ __launch_bounds__(32) void combine_kernel(
    float* __restrict__ out, int num_type)
{
    const int row  = blockIdx.x;
    const int lane = threadIdx.x;

    float p = (lane < CHUNKS) ? g_partial[row * CHUNKS + lane] : 0.0f;
    #pragma unroll
    for (int o = 16; o > 0; o >>= 1)
        p += __shfl_down_sync(0xffffffffu, p, o);

    if (lane == 0) {
        const float c0 = EPS / (float)num_type;
        out[row] = -((-LN2 * c0) * p + g_sparse[row]);
    }
}

extern "C" void kernel_launch(void* const* d_in, const int* in_sizes, int n_in,
                              void* d_out, int out_size)
{
    const float* output     = (const float*)d_in[0];
    const int*   label      = (const int*)d_in[1];
    const int*   test_label = (const int*)d_in[2];
    float*       out        = (float*)d_out;

    const int B        = out_size;               // 4096
    const int num_type = in_sizes[0] / B;        // 32000
    const int L        = in_sizes[1] / B;        // 50
    const int nvec4    = num_type >> 2;          // 8000
    const int f4pc     = (nvec4 + CHUNKS - 1) / CHUNKS;  // 500

    dense_partial_kernel<<<B * CHUNKS, TA>>>(output, label, test_label,
                                             num_type, L, nvec4, f4pc);
    combine_kernel<<<B, 32>>>(out, num_type);
}